// round 15
// baseline (speedup 1.0000x reference)
#include <cuda_runtime.h>

#define HID   128
#define NSTEP 128
#define MROWS 16
#define NTHR  128
#define ASTR  20               // act row stride in floats (80B, 16B-aligned rows)
#define NEGS  0.2f

// ---- dynamic smem layout (float offsets) ----
#define WB0   0
#define WB1   16384
#define HB_F  32768            // 128*ASTR = 2560 floats each
#define HT_F  (HB_F + HID * ASTR)
#define HB_P  (HT_F + HID * ASTR)
#define HT_P  (HB_P + HID * ASTR)
#define XST   (HT_P + HID * ASTR)   // xsT[12][16]
#define DSO   (XST + 192)           // delta[16]
#define SMEM_FLOATS (DSO + 16)
#define SMEM_BYTES  (SMEM_FLOATS * 4)

typedef unsigned long long u64;

// ---------- packed fp32x2 helpers ----------
__device__ __forceinline__ u64 ffma2(u64 x, u64 y, u64 c) {
    u64 d;
    asm("fma.rn.f32x2 %0, %1, %2, %3;" : "=l"(d) : "l"(x), "l"(y), "l"(c));
    return d;
}
__device__ __forceinline__ u64 pack2(float lo, float hi) {
    u64 d;
    asm("mov.b64 %0, {%1, %2};" : "=l"(d) : "f"(lo), "f"(hi));
    return d;
}
__device__ __forceinline__ void unpack2(u64 v, float& lo, float& hi) {
    asm("mov.b64 {%0, %1}, %2;" : "=f"(lo), "=f"(hi) : "l"(v));
}

// ---------- cp.async ----------
__device__ __forceinline__ void cp_async16(unsigned dst, const void* src) {
    asm volatile("cp.async.cg.shared.global [%0], [%1], 16;" :: "r"(dst), "l"(src));
}
__device__ __forceinline__ void cp_commit() {
    asm volatile("cp.async.commit_group;" ::: "memory");
}
__device__ __forceinline__ void cp_wait_all() {
    asm volatile("cp.async.wait_group 0;" ::: "memory");
}

// Plain 64KB weight copy (row-major [k][j], stride 128 floats).
__device__ __forceinline__ void prefetch_w(const float* __restrict__ src,
                                           float* dstf, int tid) {
    unsigned dstb = (unsigned)__cvta_generic_to_shared(dstf);
#pragma unroll
    for (int i = 0; i < 32; ++i) {
        const int off = (tid + i * NTHR) * 16;   // bytes
        cp_async16(dstb + off, (const char*)src + off);
    }
}

// Accumulators: a[p][m] = f32x2 pair of output rows at m-col m0+m.
// p=0: rows (j0, j0+1); p=1: (j0+2, j0+3); p=2: (j0+64, j0+65); p=3: (j0+66, j0+67).
struct Acc { u64 a[4][8]; };
__device__ __forceinline__ void acc_zero(Acc& A) {
#pragma unroll
    for (int p = 0; p < 4; ++p)
#pragma unroll
        for (int m = 0; m < 8; ++m) A.a[p][m] = 0ull;
}

// Partial GEMM over this lane's 32-row k-quarter. Strictly affine streams:
// weights advance HID floats/row (2 quads at +0 and +64), acts ASTR floats/row
// (2 quads at +0 and +4). 4 LDS.128 per 32 ffma2.
__device__ __forceinline__ void mm_pass(Acc& A, const float* __restrict__ wp,
                                        const float* __restrict__ ap) {
#pragma unroll 2
    for (int kk = 0; kk < 32; ++kk) {
        const float4 wA = *reinterpret_cast<const float4*>(wp + kk * HID);
        const float4 wB = *reinterpret_cast<const float4*>(wp + kk * HID + 64);
        const float4 aA = *reinterpret_cast<const float4*>(ap + kk * ASTR);
        const float4 aB = *reinterpret_cast<const float4*>(ap + kk * ASTR + 4);
        const u64 wp0 = pack2(wA.x, wA.y);   // natural register pairs (elidable)
        const u64 wp1 = pack2(wA.z, wA.w);
        const u64 wp2 = pack2(wB.x, wB.y);
        const u64 wp3 = pack2(wB.z, wB.w);
        const u64 a0 = pack2(aA.x, aA.x);    // 8 real dup movs
        const u64 a1 = pack2(aA.y, aA.y);
        const u64 a2 = pack2(aA.z, aA.z);
        const u64 a3 = pack2(aA.w, aA.w);
        const u64 a4 = pack2(aB.x, aB.x);
        const u64 a5 = pack2(aB.y, aB.y);
        const u64 a6 = pack2(aB.z, aB.z);
        const u64 a7 = pack2(aB.w, aB.w);
        A.a[0][0] = ffma2(wp0, a0, A.a[0][0]);
        A.a[0][1] = ffma2(wp0, a1, A.a[0][1]);
        A.a[0][2] = ffma2(wp0, a2, A.a[0][2]);
        A.a[0][3] = ffma2(wp0, a3, A.a[0][3]);
        A.a[0][4] = ffma2(wp0, a4, A.a[0][4]);
        A.a[0][5] = ffma2(wp0, a5, A.a[0][5]);
        A.a[0][6] = ffma2(wp0, a6, A.a[0][6]);
        A.a[0][7] = ffma2(wp0, a7, A.a[0][7]);
        A.a[1][0] = ffma2(wp1, a0, A.a[1][0]);
        A.a[1][1] = ffma2(wp1, a1, A.a[1][1]);
        A.a[1][2] = ffma2(wp1, a2, A.a[1][2]);
        A.a[1][3] = ffma2(wp1, a3, A.a[1][3]);
        A.a[1][4] = ffma2(wp1, a4, A.a[1][4]);
        A.a[1][5] = ffma2(wp1, a5, A.a[1][5]);
        A.a[1][6] = ffma2(wp1, a6, A.a[1][6]);
        A.a[1][7] = ffma2(wp1, a7, A.a[1][7]);
        A.a[2][0] = ffma2(wp2, a0, A.a[2][0]);
        A.a[2][1] = ffma2(wp2, a1, A.a[2][1]);
        A.a[2][2] = ffma2(wp2, a2, A.a[2][2]);
        A.a[2][3] = ffma2(wp2, a3, A.a[2][3]);
        A.a[2][4] = ffma2(wp2, a4, A.a[2][4]);
        A.a[2][5] = ffma2(wp2, a5, A.a[2][5]);
        A.a[2][6] = ffma2(wp2, a6, A.a[2][6]);
        A.a[2][7] = ffma2(wp2, a7, A.a[2][7]);
        A.a[3][0] = ffma2(wp3, a0, A.a[3][0]);
        A.a[3][1] = ffma2(wp3, a1, A.a[3][1]);
        A.a[3][2] = ffma2(wp3, a2, A.a[3][2]);
        A.a[3][3] = ffma2(wp3, a3, A.a[3][3]);
        A.a[3][4] = ffma2(wp3, a4, A.a[3][4]);
        A.a[3][5] = ffma2(wp3, a5, A.a[3][5]);
        A.a[3][6] = ffma2(wp3, a6, A.a[3][6]);
        A.a[3][7] = ffma2(wp3, a7, A.a[3][7]);
    }
}

// 2-level butterfly k-reduction (lane bits 3,4) + SEL pair kq + bias +
// optional residual + leaky + store. Lane (t,kq) stores rows r1, r1+1.
__device__ __forceinline__ void epi(Acc& A, const float* __restrict__ bias,
                                    float* __restrict__ dst,
                                    const float* __restrict__ res, bool hasRes,
                                    int r1, int m0, int kq) {
#pragma unroll
    for (int p = 0; p < 4; ++p)
#pragma unroll
        for (int m = 0; m < 8; ++m) {
            float lo, hi;
            unpack2(A.a[p][m], lo, hi);
            lo += __shfl_xor_sync(0xffffffffu, lo, 8);
            hi += __shfl_xor_sync(0xffffffffu, hi, 8);
            lo += __shfl_xor_sync(0xffffffffu, lo, 16);
            hi += __shfl_xor_sync(0xffffffffu, hi, 16);
            A.a[p][m] = pack2(lo, hi);
        }
    float x[8], y[8];
#pragma unroll
    for (int m = 0; m < 8; ++m) {
        const u64 u = (kq & 1) ? A.a[1][m] : A.a[0][m];
        const u64 v = (kq & 1) ? A.a[3][m] : A.a[2][m];
        const u64 w = (kq & 2) ? v : u;
        unpack2(w, x[m], y[m]);
    }
    const float b1 = __ldg(bias + r1);
    const float b2 = __ldg(bias + r1 + 1);
#pragma unroll
    for (int m = 0; m < 8; ++m) { x[m] += b1; y[m] += b2; }
    const int a1o = r1 * ASTR + m0;
    const int a2o = a1o + ASTR;
    if (hasRes) {
        const float4 rA = *reinterpret_cast<const float4*>(res + a1o);
        const float4 rB = *reinterpret_cast<const float4*>(res + a1o + 4);
        const float4 rC = *reinterpret_cast<const float4*>(res + a2o);
        const float4 rD = *reinterpret_cast<const float4*>(res + a2o + 4);
        x[0] += rA.x; x[1] += rA.y; x[2] += rA.z; x[3] += rA.w;
        x[4] += rB.x; x[5] += rB.y; x[6] += rB.z; x[7] += rB.w;
        y[0] += rC.x; y[1] += rC.y; y[2] += rC.z; y[3] += rC.w;
        y[4] += rD.x; y[5] += rD.y; y[6] += rD.z; y[7] += rD.w;
    }
#pragma unroll
    for (int m = 0; m < 8; ++m) {
        x[m] = fmaxf(x[m], NEGS * x[m]);
        y[m] = fmaxf(y[m], NEGS * y[m]);
    }
    *reinterpret_cast<float4*>(dst + a1o)     = make_float4(x[0], x[1], x[2], x[3]);
    *reinterpret_cast<float4*>(dst + a1o + 4) = make_float4(x[4], x[5], x[6], x[7]);
    *reinterpret_cast<float4*>(dst + a2o)     = make_float4(y[0], y[1], y[2], y[3]);
    *reinterpret_cast<float4*>(dst + a2o + 4) = make_float4(y[4], y[5], y[6], y[7]);
}

template <bool RES>
__device__ __forceinline__ void full_layer(const float* __restrict__ Wsm,
                                           const float* __restrict__ b,
                                           const float* __restrict__ hin,
                                           float* __restrict__ hout,
                                           int wofs, int aofs,
                                           int r1, int m0, int kq) {
    Acc A; acc_zero(A);
    mm_pass(A, Wsm + wofs, hin + aofs);
    epi(A, b, hout, hout, RES, r1, m0, kq);
}

// Small-K input layer: thread computes rows r1, r1+1, cols m0..m0+7.
__device__ __forceinline__ void input_layer(const float* __restrict__ Win,
                                            const float* __restrict__ bin,
                                            const float* __restrict__ xsT,
                                            int coff, int K,
                                            float* __restrict__ dst,
                                            int r1, int m0) {
    const int r2 = r1 + 1;
    float y1[8] = {}, y2[8] = {};
    for (int k = 0; k < K; ++k) {
        const float w1 = __ldg(Win + k * HID + r1);
        const float w2 = __ldg(Win + k * HID + r2);
        const float4 aA = *reinterpret_cast<const float4*>(xsT + (coff + k) * 16 + m0);
        const float4 aB = *reinterpret_cast<const float4*>(xsT + (coff + k) * 16 + m0 + 4);
        y1[0] = fmaf(w1, aA.x, y1[0]); y1[1] = fmaf(w1, aA.y, y1[1]);
        y1[2] = fmaf(w1, aA.z, y1[2]); y1[3] = fmaf(w1, aA.w, y1[3]);
        y1[4] = fmaf(w1, aB.x, y1[4]); y1[5] = fmaf(w1, aB.y, y1[5]);
        y1[6] = fmaf(w1, aB.z, y1[6]); y1[7] = fmaf(w1, aB.w, y1[7]);
        y2[0] = fmaf(w2, aA.x, y2[0]); y2[1] = fmaf(w2, aA.y, y2[1]);
        y2[2] = fmaf(w2, aA.z, y2[2]); y2[3] = fmaf(w2, aA.w, y2[3]);
        y2[4] = fmaf(w2, aB.x, y2[4]); y2[5] = fmaf(w2, aB.y, y2[5]);
        y2[6] = fmaf(w2, aB.z, y2[6]); y2[7] = fmaf(w2, aB.w, y2[7]);
    }
    const float b1 = __ldg(bin + r1);
    const float b2 = __ldg(bin + r2);
#pragma unroll
    for (int i = 0; i < 8; ++i) {
        y1[i] += b1; y1[i] = fmaxf(y1[i], NEGS * y1[i]);
        y2[i] += b2; y2[i] = fmaxf(y2[i], NEGS * y2[i]);
    }
    const int a1o = r1 * ASTR + m0;
    const int a2o = a1o + ASTR;
    *reinterpret_cast<float4*>(dst + a1o)     = make_float4(y1[0], y1[1], y1[2], y1[3]);
    *reinterpret_cast<float4*>(dst + a1o + 4) = make_float4(y1[4], y1[5], y1[6], y1[7]);
    *reinterpret_cast<float4*>(dst + a2o)     = make_float4(y2[0], y2[1], y2[2], y2[3]);
    *reinterpret_cast<float4*>(dst + a2o + 4) = make_float4(y2[4], y2[5], y2[6], y2[7]);
}

__global__ void __launch_bounds__(NTHR, 1)
hedger_kernel(const float* __restrict__ feats,
              const float* __restrict__ fw_in, const float* __restrict__ fb_in,
              const float* __restrict__ fr1_w1, const float* __restrict__ fr1_b1,
              const float* __restrict__ fr1_w2, const float* __restrict__ fr1_b2,
              const float* __restrict__ fr2_w1, const float* __restrict__ fr2_b1,
              const float* __restrict__ fr2_w2, const float* __restrict__ fr2_b2,
              const float* __restrict__ pw_in, const float* __restrict__ pb_in,
              const float* __restrict__ pr1_w1, const float* __restrict__ pr1_b1,
              const float* __restrict__ pr1_w2, const float* __restrict__ pr1_b2,
              const float* __restrict__ pr2_w1, const float* __restrict__ pr2_b1,
              const float* __restrict__ pr2_w2, const float* __restrict__ pr2_b2,
              const float* __restrict__ cw1, const float* __restrict__ cb1,
              const float* __restrict__ cw2, const float* __restrict__ cb2,
              float* __restrict__ out) {
    extern __shared__ float sm[];
    float* wb0  = sm + WB0;
    float* wb1  = sm + WB1;
    float* hb_f = sm + HB_F;
    float* ht_f = sm + HT_F;
    float* hb_p = sm + HB_P;
    float* ht_p = sm + HT_P;
    float* xsT  = sm + XST;
    float* ds   = sm + DSO;

    const int tid  = threadIdx.x;
    const int lane = tid & 31;
    const int warp = tid >> 5;
    const int kq   = lane >> 3;                 // 0..3 k-quarter
    const int t    = lane & 7;
    const int j0   = (warp & 1) * 32 + t * 4;   // quad A at j0, quad B at j0+64
    const int m0   = (warp >> 1) * 8;           // m-octet
    const int b0   = blockIdx.x * MROWS;

    // per-thread affine constants
    const int wofs = kq * 32 * HID + j0;        // weight base for this k-quarter
    const int aofs = kq * 32 * ASTR + m0;       // act base for this k-quarter
    const int r1   = j0 + (kq >> 1) * 64 + (kq & 1) * 2;  // store row pair

    const float cb2v = __ldg(cb2);
    const float* cw1_hi = cw1 + HID * HID;

    prefetch_w(fr1_w1, wb0, tid);
    cp_commit();

    for (int n = 0; n < NSTEP; ++n) {
        // ---- features -> xsT[c][m]; recurrent delta into col 3 ----
#pragma unroll
        for (int it = 0; it < 2; ++it) {
            const int idx = tid + it * NTHR;
            if (idx < MROWS * 12) {
                const int r = idx / 12, c = idx % 12;
                float v = feats[((size_t)(b0 + r) * NSTEP + n) * 12 + c];
                if (c == 3 && n > 0) v = ds[r];
                xsT[c * 16 + r] = v;
            }
        }
        __syncthreads();

        // ---- input layers (tiny K, weights L1-resident) ----
        input_layer(fw_in, fb_in, xsT, 0, 4, hb_f, r1, m0);
        input_layer(pw_in, pb_in, xsT, 4, 8, hb_p, r1, m0);

        // ---- 10 staged 64KB layers, double-buffered ----
        cp_wait_all(); __syncthreads();
        prefetch_w(fr1_w2, wb1, tid); cp_commit();
        full_layer<false>(wb0, fr1_b1, hb_f, ht_f, wofs, aofs, r1, m0, kq);

        cp_wait_all(); __syncthreads();
        prefetch_w(fr2_w1, wb0, tid); cp_commit();
        full_layer<true >(wb1, fr1_b2, ht_f, hb_f, wofs, aofs, r1, m0, kq);

        cp_wait_all(); __syncthreads();
        prefetch_w(fr2_w2, wb1, tid); cp_commit();
        full_layer<false>(wb0, fr2_b1, hb_f, ht_f, wofs, aofs, r1, m0, kq);

        cp_wait_all(); __syncthreads();
        prefetch_w(pr1_w1, wb0, tid); cp_commit();
        full_layer<true >(wb1, fr2_b2, ht_f, hb_f, wofs, aofs, r1, m0, kq);

        cp_wait_all(); __syncthreads();
        prefetch_w(pr1_w2, wb1, tid); cp_commit();
        full_layer<false>(wb0, pr1_b1, hb_p, ht_p, wofs, aofs, r1, m0, kq);

        cp_wait_all(); __syncthreads();
        prefetch_w(pr2_w1, wb0, tid); cp_commit();
        full_layer<true >(wb1, pr1_b2, ht_p, hb_p, wofs, aofs, r1, m0, kq);

        cp_wait_all(); __syncthreads();
        prefetch_w(pr2_w2, wb1, tid); cp_commit();
        full_layer<false>(wb0, pr2_b1, hb_p, ht_p, wofs, aofs, r1, m0, kq);

        cp_wait_all(); __syncthreads();
        prefetch_w(cw1, wb0, tid); cp_commit();
        full_layer<true >(wb1, pr2_b2, ht_p, hb_p, wofs, aofs, r1, m0, kq);

        // combiner: accumulate both halves of concat(fe, pe) @ cw1
        {
            Acc A; acc_zero(A);
            cp_wait_all(); __syncthreads();
            prefetch_w(cw1_hi, wb1, tid); cp_commit();
            mm_pass(A, wb0 + wofs, hb_f + aofs);       // fe @ cw1[0:128]

            cp_wait_all(); __syncthreads();
            prefetch_w(fr1_w1, wb0, tid); cp_commit(); // wrap: next step's L0
            mm_pass(A, wb1 + wofs, hb_p + aofs);       // pe @ cw1[128:256]
            epi(A, cb1, ht_f, ht_f, false, r1, m0, kq);
        }
        __syncthreads();

        // ---- head: sigmoid(hc @ cw2 + cb2) ----
        {
            const int m   = tid >> 3;        // 0..15
            const int seg = tid & 7;         // low 3 bits of j -> conflict-free LDS
            float pacc = 0.0f;
#pragma unroll
            for (int jj = 0; jj < 16; ++jj) {
                const int j = jj * 8 + seg;
                pacc += ht_f[j * ASTR + m] * __ldg(cw2 + j);
            }
            pacc += __shfl_down_sync(0xffffffffu, pacc, 4, 8);
            pacc += __shfl_down_sync(0xffffffffu, pacc, 2, 8);
            pacc += __shfl_down_sync(0xffffffffu, pacc, 1, 8);
            if (seg == 0) {
                const float d = 1.0f / (1.0f + expf(-(pacc + cb2v)));
                ds[m] = d;
                out[(size_t)(b0 + m) * NSTEP + n] = d;
            }
        }
        __syncthreads();
    }
}

extern "C" void kernel_launch(void* const* d_in, const int* in_sizes, int n_in,
                              void* d_out, int out_size) {
    const float* feats  = (const float*)d_in[0];
    const float* fw_in  = (const float*)d_in[1];
    const float* fb_in  = (const float*)d_in[2];
    const float* fr1_w1 = (const float*)d_in[3];
    const float* fr1_b1 = (const float*)d_in[4];
    const float* fr1_w2 = (const float*)d_in[5];
    const float* fr1_b2 = (const float*)d_in[6];
    const float* fr2_w1 = (const float*)d_in[7];
    const float* fr2_b1 = (const float*)d_in[8];
    const float* fr2_w2 = (const float*)d_in[9];
    const float* fr2_b2 = (const float*)d_in[10];
    const float* pw_in  = (const float*)d_in[11];
    const float* pb_in  = (const float*)d_in[12];
    const float* pr1_w1 = (const float*)d_in[13];
    const float* pr1_b1 = (const float*)d_in[14];
    const float* pr1_w2 = (const float*)d_in[15];
    const float* pr1_b2 = (const float*)d_in[16];
    const float* pr2_w1 = (const float*)d_in[17];
    const float* pr2_b1 = (const float*)d_in[18];
    const float* pr2_w2 = (const float*)d_in[19];
    const float* pr2_b2 = (const float*)d_in[20];
    const float* cw1    = (const float*)d_in[21];
    const float* cb1    = (const float*)d_in[22];
    const float* cw2    = (const float*)d_in[23];
    const float* cb2    = (const float*)d_in[24];

    cudaFuncSetAttribute(hedger_kernel,
                         cudaFuncAttributeMaxDynamicSharedMemorySize, SMEM_BYTES);

    hedger_kernel<<<2048 / MROWS, NTHR, SMEM_BYTES>>>(
        feats,
        fw_in, fb_in,
        fr1_w1, fr1_b1, fr1_w2, fr1_b2,
        fr2_w1, fr2_b1, fr2_w2, fr2_b2,
        pw_in, pb_in,
        pr1_w1, pr1_b1, pr1_w2, pr1_b2,
        pr2_w1, pr2_b1, pr2_w2, pr2_b2,
        cw1, cb1, cw2, cb2,
        (float*)d_out);
}